// round 11
// baseline (speedup 1.0000x reference)
#include <cuda_runtime.h>
#include <math.h>

#define BB 32
#define SS 1024
#define II 512
#define HH 512
#define GG 2048   // 4*H

typedef unsigned long long u64;

// ---------------- device scratch ----------------
__device__ float g_xt[(size_t)SS * 256 * 64];   // x transposed: [t][kpair][b][2], 64MB
__device__ float g_hb[2][HH * BB];              // h ping-pong: [kquad][b][4]
__device__ unsigned g_sub[8 * 32];              // barrier: 8 sub-counters (16 CTAs each)
__device__ unsigned g_top[32];                  // top counter
__device__ unsigned g_mail[128 * 32];           // per-CTA mailbox (128B apart)

__device__ __forceinline__ unsigned ld_acq(const unsigned* p) {
    unsigned v;
    asm volatile("ld.acquire.gpu.u32 %0, [%1];" : "=r"(v) : "l"(p));
    return v;
}
__device__ __forceinline__ void st_rel(unsigned* p, unsigned v) {
    asm volatile("st.release.gpu.u32 [%0], %1;" :: "l"(p), "r"(v));
}
__device__ __forceinline__ u64 fma2(u64 a, u64 b, u64 c) {
    u64 d;
    asm("fma.rn.f32x2 %0, %1, %2, %3;" : "=l"(d) : "l"(a), "l"(b), "l"(c));
    return d;
}
__device__ __forceinline__ u64 add2(u64 a, u64 b) {
    u64 d;
    asm("add.rn.f32x2 %0, %1, %2;" : "=l"(d) : "l"(a), "l"(b));
    return d;
}
__device__ __forceinline__ float2 unpack2(u64 v) {
    unsigned lo, hi;
    asm("mov.b64 {%0, %1}, %2;" : "=r"(lo), "=r"(hi) : "l"(v));
    return make_float2(__uint_as_float(lo), __uint_as_float(hi));
}
__device__ __forceinline__ u64 ldcg_u64(const u64* p) {
    u64 v;
    asm volatile("ld.global.cg.u64 %0, [%1];" : "=l"(v) : "l"(p));
    return v;
}
__device__ __forceinline__ ulonglong2 ldcg_v2u64(const void* p) {
    ulonglong2 v;
    asm volatile("ld.global.cg.v2.u64 {%0, %1}, [%2];"
                 : "=l"(v.x), "=l"(v.y) : "l"(p));
    return v;
}
__device__ __forceinline__ void stcg_v4f32(float* p, float a, float b, float c, float d) {
    asm volatile("st.global.cg.v4.f32 [%0], {%1, %2, %3, %4};"
                 :: "l"(p), "f"(a), "f"(b), "f"(c), "f"(d));
}
__device__ __forceinline__ float sigmoid_fast(float x) {
    return __fdividef(1.f, 1.f + __expf(-x));
}
__device__ __forceinline__ float tanh_fast(float x) {
    float e2 = __expf(2.f * fabsf(x));
    float r  = 1.f - __fdividef(2.f, e2 + 1.f);
    return copysignf(r, x);
}

// =====================================================================
// Kernel 1 (one-time ~30us): x[b][t][k] -> g_xt[t][kpair][b][2]
// =====================================================================
__global__ void __launch_bounds__(256) xpose(const float* __restrict__ x)
{
    extern __shared__ float xs[];   // 32 x 513
    const int t   = blockIdx.x;
    const int tid = threadIdx.x;
#pragma unroll
    for (int it = 0; it < 16; it++) {
        int b  = it * 2 + (tid >> 7);
        int k4 = (tid & 127) << 2;
        float4 v = *(const float4*)&x[((size_t)b * SS + t) * II + k4];
        xs[b * 513 + k4 + 0] = v.x;
        xs[b * 513 + k4 + 1] = v.y;
        xs[b * 513 + k4 + 2] = v.z;
        xs[b * 513 + k4 + 3] = v.w;
    }
    __syncthreads();
#pragma unroll
    for (int it = 0; it < 32; it++) {
        int idx = tid + it * 256;      // 8192 = 256 kp x 32 b
        int kp  = idx >> 5;
        int b   = idx & 31;
        float lo = xs[b * 513 + 2 * kp];
        float hi = xs[b * 513 + 2 * kp + 1];
        *(float2*)&g_xt[((size_t)t * 256 + kp) * 64 + b * 2] = make_float2(lo, hi);
    }
}

// =====================================================================
// warp-collective arrive (warp 0). Completer's warp broadcasts the new
// window to all 128 mailboxes. Window SS resets all state (graph replay).
// =====================================================================
__device__ __forceinline__ void arrive_warp(unsigned win, int cta, int lane)
{
    unsigned completer = 0;
    if (lane == 0) {
        unsigned old;
        int sb = cta & 7;
        asm volatile("atom.acq_rel.gpu.global.add.u32 %0, [%1], %2;"
                     : "=r"(old) : "l"(&g_sub[sb * 32]), "r"(1u));
        if (old == win * 16u + 15u) {
            asm volatile("atom.acq_rel.gpu.global.add.u32 %0, [%1], %2;"
                         : "=r"(old) : "l"(&g_top[0]), "r"(1u));
            if (old == win * 8u + 7u) completer = 1u;
        }
    }
    completer = __shfl_sync(0xffffffffu, completer, 0);
    if (completer) {
        unsigned val = (win < (unsigned)SS) ? win + 1u : 0u;
        if (lane == 0 && win == (unsigned)SS) {
#pragma unroll
            for (int i = 0; i < 8; i++) g_sub[i * 32] = 0;
            g_top[0] = 0;
        }
#pragma unroll
        for (int i = 0; i < 4; i++)
            st_rel(&g_mail[(lane + i * 32) * 32], val);
    }
}

// 16 rows x 32-k chunk; warp-uniform W (1 wf per LDS.128); 2 acc banks
__device__ __forceinline__ void fma_chunk32(
    const float* __restrict__ Wp, const u64* __restrict__ v2,
    float* __restrict__ sums, int kb)
{
#pragma unroll
    for (int r0 = 0; r0 < 16; r0 += 4) {
        u64 a0[4], a1[4];
#pragma unroll
        for (int rr = 0; rr < 4; rr++) { a0[rr] = 0ull; a1[rr] = 0ull; }
#pragma unroll
        for (int q = 0; q < 8; q++) {
#pragma unroll
            for (int rr = 0; rr < 4; rr++) {
                ulonglong2 wv = *(const ulonglong2*)&Wp[(r0 + rr) * 512 + kb + q * 4];
                a0[rr] = fma2(wv.x, v2[2 * q + 0], a0[rr]);
                a1[rr] = fma2(wv.y, v2[2 * q + 1], a1[rr]);
            }
        }
#pragma unroll
        for (int rr = 0; rr < 4; rr++) {
            float2 f = unpack2(add2(a0[rr], a1[rr]));
            sums[r0 + rr] += f.x + f.y;
        }
    }
}

// =====================================================================
// Kernel 2: fused persistent LSTM. 128 CTAs x 256 thr.
// CTA owns 4 h-idx (16 gate rows); warp owns 64-k chunk; lane = batch.
// Pipelined step: x-FMA (shadow work) -> private-mailbox wait -> h load
// + x(t+1) half-prefetch -> h-FMA -> STS(part[t&1]) ->
//   warps 1-7: bar.arrive, run ahead into t+1 x-FMA
//   warp 0:    bar.sync, reduce + nonlin + stores, arrive (broadcast)
// =====================================================================
__global__ void __launch_bounds__(256, 1) lstm_rec(
    const float* __restrict__ Wih, const float* __restrict__ Whh,
    const float* __restrict__ bih, const float* __restrict__ bhh,
    const float* __restrict__ h0, const float* __restrict__ c0,
    float* __restrict__ out, int write_hc)
{
    extern __shared__ float sm[];
    float* Wih_s = sm;                 // 16 x 512 = 32KB
    float* Whh_s = sm + 8192;          // 32KB
    float* part0 = sm + 16384;         // [16 rows][8 w][32 b] = 16KB
    float* part1 = sm + 20480;         // double buffer

    const int tid  = threadIdx.x;
    const int w    = tid >> 5;
    const int lane = tid & 31;         // lane = batch
    const int cta  = blockIdx.x;
    const int j0   = cta * 4;
    const int kb   = w * 64;

    // ---- load W slices (16 rows x 512 each), rows r = type*4 + j ----
#pragma unroll
    for (int s = 0; s < 16; s++) {
        int idx = tid + s * 256;              // 4096 float4 slots
        int mat = idx >> 11;
        int rr  = (idx & 2047) >> 7;
        int k4  = (idx & 127) << 2;
        int g   = (rr >> 2) * 512 + j0 + (rr & 3);
        float* dst = (mat ? Whh_s : Wih_s) + rr * 512 + k4;
        const float* src = (mat ? Whh : Wih) + (size_t)g * 512 + k4;
        *(float4*)dst = *(const float4*)src;
    }

    // ---- warp 0 state: lane = batch; c + biases for j0..j0+3 ----
    float4 creg = make_float4(0.f, 0.f, 0.f, 0.f);
    float4 bias[4];
    if (w == 0) {
        creg = *(const float4*)&c0[(size_t)lane * HH + j0];
        float4 hv = *(const float4*)&h0[(size_t)lane * HH + j0];
        stcg_v4f32(&g_hb[0][cta * 128 + lane * 4], hv.x, hv.y, hv.z, hv.w);
#pragma unroll
        for (int t4 = 0; t4 < 4; t4++) {
            float4 b1 = *(const float4*)&bih[t4 * 512 + j0];
            float4 b2 = *(const float4*)&bhh[t4 * 512 + j0];
            bias[t4] = make_float4(b1.x + b2.x, b1.y + b2.y, b1.z + b2.z, b1.w + b2.w);
        }
    }
    __syncthreads();
    if (w == 0) arrive_warp(0u, cta, lane);   // window 0: h0 published

    const u64* xt64 = (const u64*)g_xt;
    const unsigned* mybox = &g_mail[cta * 32];

    // prefetch x half A for t = 0
    u64 xa[16];
#pragma unroll
    for (int i = 0; i < 16; i++)
        xa[i] = ldcg_u64(&xt64[((size_t)0 * 256 + w * 32 + i) * 32 + lane]);

#pragma unroll 1
    for (int t = 0; t < SS; t++) {
        float sums[16];
#pragma unroll
        for (int r = 0; r < 16; r++) sums[r] = 0.f;

        // ---- x-FMA half A (prefetched), load half B, x-FMA half B ----
        fma_chunk32(Wih_s, xa, sums, kb);
        u64 xbv[16];
#pragma unroll
        for (int i = 0; i < 16; i++)
            xbv[i] = ldcg_u64(&xt64[((size_t)t * 256 + w * 32 + 16 + i) * 32 + lane]);
        fma_chunk32(Wih_s, xbv, sums, kb + 32);

        // ---- wait on private mailbox: h(t) published ----
        while (ld_acq(mybox) < (unsigned)(t + 1)) { }

        // ---- h loads (16 x LDG.128), then x(t+1) half-A prefetch ----
        const ulonglong2* hb128 = (const ulonglong2*)g_hb[t & 1];
        u64 h2[32];
#pragma unroll
        for (int i = 0; i < 16; i++) {
            ulonglong2 v = ldcg_v2u64(&hb128[(w * 16 + i) * 32 + lane]);
            h2[2 * i + 0] = v.x;
            h2[2 * i + 1] = v.y;
        }
        int tn = (t + 1 < SS) ? (t + 1) : t;
#pragma unroll
        for (int i = 0; i < 16; i++)
            xa[i] = ldcg_u64(&xt64[((size_t)tn * 256 + w * 32 + i) * 32 + lane]);

        // ---- h-FMA ----
        fma_chunk32(Whh_s, h2,      sums, kb);
        fma_chunk32(Whh_s, h2 + 16, sums, kb + 32);

        float* part = (t & 1) ? part1 : part0;
#pragma unroll
        for (int r = 0; r < 16; r++)
            part[r * 256 + w * 32 + lane] = sums[r];

        if (w != 0) {
            // non-blocking arrive; run ahead into t+1's x-FMA.
            // part[t&1] reuse at t+2 is gated by window t+1 (warp0 reduce).
            asm volatile("bar.arrive 1, 256;" ::: "memory");
        } else {
            asm volatile("bar.sync 1, 256;" ::: "memory");

            float gate[4][4];   // [type][j]
#pragma unroll
            for (int t4 = 0; t4 < 4; t4++) {
                float bv[4] = {bias[t4].x, bias[t4].y, bias[t4].z, bias[t4].w};
#pragma unroll
                for (int j = 0; j < 4; j++) {
                    int r = t4 * 4 + j;
                    float s = bv[j];
#pragma unroll
                    for (int ww = 0; ww < 8; ww++)
                        s += part[r * 256 + ww * 32 + lane];
                    gate[t4][j] = s;
                }
            }
            float hv[4], cv[4];
            float cr[4] = {creg.x, creg.y, creg.z, creg.w};
#pragma unroll
            for (int j = 0; j < 4; j++) {
                float ig = sigmoid_fast(gate[0][j]);
                float fg = sigmoid_fast(gate[1][j]);
                float gg = tanh_fast(gate[2][j]);
                float og = sigmoid_fast(gate[3][j]);
                float c  = fg * cr[j] + ig * gg;
                cv[j] = c;
                hv[j] = og * tanh_fast(c);
            }
            creg = make_float4(cv[0], cv[1], cv[2], cv[3]);

            stcg_v4f32(&g_hb[(t + 1) & 1][cta * 128 + lane * 4],
                       hv[0], hv[1], hv[2], hv[3]);
            *(float4*)&out[((size_t)lane * SS + t) * HH + j0] =
                make_float4(hv[0], hv[1], hv[2], hv[3]);
            if (t == SS - 1 && write_hc) {
                size_t base = (size_t)BB * SS * HH;
                *(float4*)&out[base + (size_t)lane * HH + j0] =
                    make_float4(hv[0], hv[1], hv[2], hv[3]);
                *(float4*)&out[base + (size_t)BB * HH + (size_t)lane * HH + j0] =
                    make_float4(cv[0], cv[1], cv[2], cv[3]);
            }
            __syncwarp();
            arrive_warp((unsigned)(t + 1), cta, lane);
        }
    }
}

// =====================================================================
extern "C" void kernel_launch(void* const* d_in, const int* in_sizes, int n_in,
                              void* d_out, int out_size)
{
    const float* x   = (const float*)d_in[0];
    const float* Wih = (const float*)d_in[1];
    const float* Whh = (const float*)d_in[2];
    const float* bih = (const float*)d_in[3];
    const float* bhh = (const float*)d_in[4];
    const float* h0  = (const float*)d_in[5];
    const float* c0  = (const float*)d_in[6];
    float* out = (float*)d_out;

    long long need = (long long)BB * SS * HH + 2LL * BB * HH;
    int write_hc = ((long long)out_size >= need) ? 1 : 0;

    int xpose_smem = 32 * 513 * (int)sizeof(float);                  // ~64KB
    int rec_smem   = (32 * 512 + 2 * 16 * 256) * (int)sizeof(float); // 96KB
    cudaFuncSetAttribute(xpose, cudaFuncAttributeMaxDynamicSharedMemorySize, xpose_smem);
    cudaFuncSetAttribute(lstm_rec, cudaFuncAttributeMaxDynamicSharedMemorySize, rec_smem);

    xpose<<<SS, 256, xpose_smem>>>(x);
    lstm_rec<<<128, 256, rec_smem>>>(Wih, Whh, bih, bhh, h0, c0, out, write_hc);
}

// round 12
// speedup vs baseline: 1.1116x; 1.1116x over previous
#include <cuda_runtime.h>
#include <math.h>

#define BB 32
#define SS 1024
#define II 512
#define HH 512
#define GG 2048   // 4*H

typedef unsigned long long u64;

// ---------------- device scratch ----------------
__device__ float g_xt[(size_t)SS * 256 * 64];   // x transposed: [t][kpair][b][2], 64MB
__device__ float g_hb[2][HH * BB];              // h ping-pong: [kquad][b][4]
__device__ unsigned g_sub[16 * 32];             // barrier: 16 sub-counters (16 CTAs each)
__device__ unsigned g_top[32];                  // top counter (16 subs)
__device__ unsigned g_genrep[8 * 32];           // replicated gen lines (128B apart)

__device__ __forceinline__ unsigned ld_acq(const unsigned* p) {
    unsigned v;
    asm volatile("ld.acquire.gpu.u32 %0, [%1];" : "=r"(v) : "l"(p));
    return v;
}
__device__ __forceinline__ void st_rel(unsigned* p, unsigned v) {
    asm volatile("st.release.gpu.u32 [%0], %1;" :: "l"(p), "r"(v));
}
__device__ __forceinline__ u64 fma2(u64 a, u64 b, u64 c) {
    u64 d;
    asm("fma.rn.f32x2 %0, %1, %2, %3;" : "=l"(d) : "l"(a), "l"(b), "l"(c));
    return d;
}
__device__ __forceinline__ u64 add2(u64 a, u64 b) {
    u64 d;
    asm("add.rn.f32x2 %0, %1, %2;" : "=l"(d) : "l"(a), "l"(b));
    return d;
}
__device__ __forceinline__ float2 unpack2(u64 v) {
    unsigned lo, hi;
    asm("mov.b64 {%0, %1}, %2;" : "=r"(lo), "=r"(hi) : "l"(v));
    return make_float2(__uint_as_float(lo), __uint_as_float(hi));
}
__device__ __forceinline__ u64 ldcg_u64(const u64* p) {
    u64 v;
    asm volatile("ld.global.cg.u64 %0, [%1];" : "=l"(v) : "l"(p));
    return v;
}
__device__ __forceinline__ ulonglong2 ldcg_v2u64(const void* p) {
    ulonglong2 v;
    asm volatile("ld.global.cg.v2.u64 {%0, %1}, [%2];"
                 : "=l"(v.x), "=l"(v.y) : "l"(p));
    return v;
}
__device__ __forceinline__ void stcg_v2f32(float* p, float a, float b) {
    asm volatile("st.global.cg.v2.f32 [%0], {%1, %2};" :: "l"(p), "f"(a), "f"(b));
}
__device__ __forceinline__ float sigmoid_fast(float x) {
    return __fdividef(1.f, 1.f + __expf(-x));
}
__device__ __forceinline__ float tanh_fast(float x) {
    float e2 = __expf(2.f * fabsf(x));
    float r  = 1.f - __fdividef(2.f, e2 + 1.f);
    return copysignf(r, x);
}

// =====================================================================
// Kernel 1 (one-time ~30us): x[b][t][k] -> g_xt[t][kpair][b][2]
// =====================================================================
__global__ void __launch_bounds__(256) xpose(const float* __restrict__ x)
{
    extern __shared__ float xs[];   // 32 x 513
    const int t   = blockIdx.x;
    const int tid = threadIdx.x;
#pragma unroll
    for (int it = 0; it < 16; it++) {
        int b  = it * 2 + (tid >> 7);
        int k4 = (tid & 127) << 2;
        float4 v = *(const float4*)&x[((size_t)b * SS + t) * II + k4];
        xs[b * 513 + k4 + 0] = v.x;
        xs[b * 513 + k4 + 1] = v.y;
        xs[b * 513 + k4 + 2] = v.z;
        xs[b * 513 + k4 + 3] = v.w;
    }
    __syncthreads();
#pragma unroll
    for (int it = 0; it < 32; it++) {
        int idx = tid + it * 256;      // 8192 = 256 kp x 32 b
        int kp  = idx >> 5;
        int b   = idx & 31;
        float lo = xs[b * 513 + 2 * kp];
        float hi = xs[b * 513 + 2 * kp + 1];
        *(float2*)&g_xt[((size_t)t * 256 + kp) * 64 + b * 2] = make_float2(lo, hi);
    }
}

// =====================================================================
// warp-collective arrive (warp 0). 256 CTAs: 16 subs x 16, top counts 16.
// Completer fences then broadcasts the window to 8 replicated gen lines.
// Window SS resets all state (graph replay).
// =====================================================================
__device__ __forceinline__ void arrive_warp(unsigned win, int cta, int lane)
{
    unsigned completer = 0;
    if (lane == 0) {
        unsigned old;
        int sb = cta & 15;
        asm volatile("atom.acq_rel.gpu.global.add.u32 %0, [%1], %2;"
                     : "=r"(old) : "l"(&g_sub[sb * 32]), "r"(1u));
        if (old == win * 16u + 15u) {
            asm volatile("atom.acq_rel.gpu.global.add.u32 %0, [%1], %2;"
                         : "=r"(old) : "l"(&g_top[0]), "r"(1u));
            if (old == win * 16u + 15u) completer = 1u;
        }
    }
    completer = __shfl_sync(0xffffffffu, completer, 0);
    if (completer) {
        unsigned val = (win < (unsigned)SS) ? win + 1u : 0u;
        if (lane == 0 && win == (unsigned)SS) {
#pragma unroll
            for (int i = 0; i < 16; i++) g_sub[i * 32] = 0;
            g_top[0] = 0;
        }
        asm volatile("fence.acq_rel.gpu;" ::: "memory");
        if (lane < 8) st_rel(&g_genrep[lane * 32], val);
    }
}

// 8 rows x 64-k (32 u64); warp-uniform W (1 wf per LDS.128); 2 acc banks
__device__ __forceinline__ void fma_chunk64(
    const float* __restrict__ Wp, const u64* __restrict__ v2,
    float* __restrict__ sums, int kb)
{
#pragma unroll
    for (int r0 = 0; r0 < 8; r0 += 4) {
        u64 a0[4], a1[4];
#pragma unroll
        for (int rr = 0; rr < 4; rr++) { a0[rr] = 0ull; a1[rr] = 0ull; }
#pragma unroll
        for (int q = 0; q < 16; q++) {
#pragma unroll
            for (int rr = 0; rr < 4; rr++) {
                ulonglong2 wv = *(const ulonglong2*)&Wp[(r0 + rr) * 512 + kb + q * 4];
                a0[rr] = fma2(wv.x, v2[2 * q + 0], a0[rr]);
                a1[rr] = fma2(wv.y, v2[2 * q + 1], a1[rr]);
            }
        }
#pragma unroll
        for (int rr = 0; rr < 4; rr++) {
            float2 f = unpack2(add2(a0[rr], a1[rr]));
            sums[r0 + rr] += f.x + f.y;
        }
    }
}

// =====================================================================
// Kernel 2: fused persistent LSTM. 256 CTAs x 128 thr (2 CTAs/SM).
// CTA owns 2 h-idx (8 gate rows); warp owns a 128-k chunk; lane = batch.
// R6 step structure: x-FMA (hides wait) -> gen wait -> h-load -> h-FMA
// -> STS -> sync -> warp0 reduce/nonlin/store/arrive, others run ahead.
// =====================================================================
__global__ void __launch_bounds__(128, 2) lstm_rec(
    const float* __restrict__ Wih, const float* __restrict__ Whh,
    const float* __restrict__ bih, const float* __restrict__ bhh,
    const float* __restrict__ h0, const float* __restrict__ c0,
    float* __restrict__ out, int write_hc)
{
    extern __shared__ float sm[];
    float* Wih_s = sm;                 // 8 x 512 = 16KB
    float* Whh_s = sm + 4096;          // 16KB
    float* part  = sm + 8192;          // [8 rows][4 w][32 b] = 4KB

    const int tid  = threadIdx.x;
    const int w    = tid >> 5;
    const int lane = tid & 31;         // lane = batch
    const int cta  = blockIdx.x;
    const int j0   = cta * 2;          // 2 h-indices per CTA
    const int kb   = w * 128;          // this warp's k chunk (floats)

    // ---- load W slices (8 rows x 512 each), rows r = type*2 + jj ----
#pragma unroll
    for (int s = 0; s < 16; s++) {
        int idx = tid + s * 128;              // 2048 float4 slots
        int mat = idx >> 10;                  // 0 = Wih, 1 = Whh
        int rr  = (idx & 1023) >> 7;
        int k4  = (idx & 127) << 2;
        int g   = (rr >> 1) * 512 + j0 + (rr & 1);
        float* dst = (mat ? Whh_s : Wih_s) + rr * 512 + k4;
        const float* src = (mat ? Whh : Wih) + (size_t)g * 512 + k4;
        *(float4*)dst = *(const float4*)src;
    }

    // ---- warp 0 state: lane = batch; c + biases for j0, j0+1 ----
    float2 creg = make_float2(0.f, 0.f);
    float2 bias[4];
    if (w == 0) {
        creg = *(const float2*)&c0[(size_t)lane * HH + j0];
        float2 hv = *(const float2*)&h0[(size_t)lane * HH + j0];
        stcg_v2f32(&g_hb[0][(j0 >> 2) * 128 + lane * 4 + (j0 & 3)], hv.x, hv.y);
#pragma unroll
        for (int t4 = 0; t4 < 4; t4++) {
            float2 b1 = *(const float2*)&bih[t4 * 512 + j0];
            float2 b2 = *(const float2*)&bhh[t4 * 512 + j0];
            bias[t4] = make_float2(b1.x + b2.x, b1.y + b2.y);
        }
    }
    __syncthreads();
    if (w == 0) arrive_warp(0u, cta, lane);   // window 0: h0 published

    const u64* xt64 = (const u64*)g_xt;
    const unsigned* mygen = &g_genrep[(cta & 7) * 32];

#pragma unroll 1
    for (int t = 0; t < SS; t++) {
        float sums[8];
#pragma unroll
        for (int r = 0; r < 8; r++) sums[r] = 0.f;

        // ---- phase A: x contribution in two 64-k halves ----
        {
            u64 xv[32];
#pragma unroll
            for (int i = 0; i < 32; i++)
                xv[i] = ldcg_u64(&xt64[((size_t)t * 256 + w * 64 + i) * 32 + lane]);
            fma_chunk64(Wih_s, xv, sums, kb);
#pragma unroll
            for (int i = 0; i < 32; i++)
                xv[i] = ldcg_u64(&xt64[((size_t)t * 256 + w * 64 + 32 + i) * 32 + lane]);
            fma_chunk64(Wih_s, xv, sums, kb + 64);
        }

        // ---- wait: h(t) published (replicated gen line) ----
        while (ld_acq(mygen) < (unsigned)(t + 1)) { }

        // ---- phase B: h contribution in two 64-k halves ----
        {
            const ulonglong2* hb128 = (const ulonglong2*)g_hb[t & 1];
            u64 hv[32];
#pragma unroll
            for (int i = 0; i < 16; i++) {
                ulonglong2 v = ldcg_v2u64(&hb128[(w * 32 + i) * 32 + lane]);
                hv[2 * i + 0] = v.x;
                hv[2 * i + 1] = v.y;
            }
            fma_chunk64(Whh_s, hv, sums, kb);
#pragma unroll
            for (int i = 0; i < 16; i++) {
                ulonglong2 v = ldcg_v2u64(&hb128[(w * 32 + 16 + i) * 32 + lane]);
                hv[2 * i + 0] = v.x;
                hv[2 * i + 1] = v.y;
            }
            fma_chunk64(Whh_s, hv, sums, kb + 64);
        }

#pragma unroll
        for (int r = 0; r < 8; r++)
            part[r * 128 + w * 32 + lane] = sums[r];
        __syncthreads();

        // ---- warp 0: reduce + nonlinearity + stores + arrive ----
        if (w == 0) {
            float gate[4][2];   // [type][jj]
#pragma unroll
            for (int t4 = 0; t4 < 4; t4++) {
                float bv[2] = {bias[t4].x, bias[t4].y};
#pragma unroll
                for (int jj = 0; jj < 2; jj++) {
                    int r = t4 * 2 + jj;
                    float s = bv[jj];
#pragma unroll
                    for (int ww = 0; ww < 4; ww++)
                        s += part[r * 128 + ww * 32 + lane];
                    gate[t4][jj] = s;
                }
            }
            float hvv[2], cvv[2];
            float cr[2] = {creg.x, creg.y};
#pragma unroll
            for (int jj = 0; jj < 2; jj++) {
                float ig = sigmoid_fast(gate[0][jj]);
                float fg = sigmoid_fast(gate[1][jj]);
                float gg = tanh_fast(gate[2][jj]);
                float og = sigmoid_fast(gate[3][jj]);
                float c  = fg * cr[jj] + ig * gg;
                cvv[jj] = c;
                hvv[jj] = og * tanh_fast(c);
            }
            creg = make_float2(cvv[0], cvv[1]);

            stcg_v2f32(&g_hb[(t + 1) & 1][(j0 >> 2) * 128 + lane * 4 + (j0 & 3)],
                       hvv[0], hvv[1]);
            *(float2*)&out[((size_t)lane * SS + t) * HH + j0] =
                make_float2(hvv[0], hvv[1]);
            if (t == SS - 1 && write_hc) {
                size_t base = (size_t)BB * SS * HH;
                *(float2*)&out[base + (size_t)lane * HH + j0] =
                    make_float2(hvv[0], hvv[1]);
                *(float2*)&out[base + (size_t)BB * HH + (size_t)lane * HH + j0] =
                    make_float2(cvv[0], cvv[1]);
            }
            __syncwarp();
            arrive_warp((unsigned)(t + 1), cta, lane);
        }
        // warps 1-3 run ahead into t+1's x-FMA; part overwrite at t+1 is
        // gated by the gen wait (needs our warp0's arrive).
    }
}

// =====================================================================
extern "C" void kernel_launch(void* const* d_in, const int* in_sizes, int n_in,
                              void* d_out, int out_size)
{
    const float* x   = (const float*)d_in[0];
    const float* Wih = (const float*)d_in[1];
    const float* Whh = (const float*)d_in[2];
    const float* bih = (const float*)d_in[3];
    const float* bhh = (const float*)d_in[4];
    const float* h0  = (const float*)d_in[5];
    const float* c0  = (const float*)d_in[6];
    float* out = (float*)d_out;

    long long need = (long long)BB * SS * HH + 2LL * BB * HH;
    int write_hc = ((long long)out_size >= need) ? 1 : 0;

    int xpose_smem = 32 * 513 * (int)sizeof(float);                  // ~64KB
    int rec_smem   = (16 * 512 + 8 * 128) * (int)sizeof(float);      // 36KB
    cudaFuncSetAttribute(xpose, cudaFuncAttributeMaxDynamicSharedMemorySize, xpose_smem);
    cudaFuncSetAttribute(lstm_rec, cudaFuncAttributeMaxDynamicSharedMemorySize, rec_smem);

    xpose<<<SS, 256, xpose_smem>>>(x);
    lstm_rec<<<256, 128, rec_smem>>>(Wih, Whh, bih, bhh, h0, c0, out, write_hc);
}

// round 13
// speedup vs baseline: 1.6731x; 1.5051x over previous
#include <cuda_runtime.h>
#include <math.h>

#define BB 32
#define SS 1024
#define II 512
#define HH 512

typedef unsigned long long u64;

// ---------------- device scratch ----------------
__device__ float g_xt[(size_t)SS * 16384];   // x transposed: [t][kquad][b][4], 64MB
__device__ float g_hb[2][HH * BB];           // h ping-pong: [kquad][b][4]
__device__ unsigned g_bkt[8 * 4 * 32];       // 8 buckets x 4 replicated copies (128B apart)
__device__ unsigned g_end;                   // end-of-kernel cleanup counter

__device__ __forceinline__ unsigned ld_acq(const unsigned* p) {
    unsigned v;
    asm volatile("ld.acquire.gpu.u32 %0, [%1];" : "=r"(v) : "l"(p));
    return v;
}
__device__ __forceinline__ u64 fma2(u64 a, u64 b, u64 c) {
    u64 d;
    asm("fma.rn.f32x2 %0, %1, %2, %3;" : "=l"(d) : "l"(a), "l"(b), "l"(c));
    return d;
}
__device__ __forceinline__ u64 add2(u64 a, u64 b) {
    u64 d;
    asm("add.rn.f32x2 %0, %1, %2;" : "=l"(d) : "l"(a), "l"(b));
    return d;
}
__device__ __forceinline__ float2 unpack2(u64 v) {
    unsigned lo, hi;
    asm("mov.b64 {%0, %1}, %2;" : "=r"(lo), "=r"(hi) : "l"(v));
    return make_float2(__uint_as_float(lo), __uint_as_float(hi));
}
__device__ __forceinline__ ulonglong2 ldcg_v2u64(const void* p) {
    ulonglong2 v;
    asm volatile("ld.global.cg.v2.u64 {%0, %1}, [%2];"
                 : "=l"(v.x), "=l"(v.y) : "l"(p));
    return v;
}
__device__ __forceinline__ void stcg_v4f32(float* p, float a, float b, float c, float d) {
    asm volatile("st.global.cg.v4.f32 [%0], {%1, %2, %3, %4};"
                 :: "l"(p), "f"(a), "f"(b), "f"(c), "f"(d));
}
__device__ __forceinline__ float sigmoid_fast(float x) {
    return __fdividef(1.f, 1.f + __expf(-x));
}
__device__ __forceinline__ float tanh_fast(float x) {
    float e2 = __expf(2.f * fabsf(x));
    float r  = 1.f - __fdividef(2.f, e2 + 1.f);
    return copysignf(r, x);
}

// =====================================================================
// Kernel 1 (one-time ~30us): x[b][t][k] -> g_xt[t][kquad][b][4]
// =====================================================================
__global__ void __launch_bounds__(256) xpose(const float* __restrict__ x)
{
    extern __shared__ float xs[];   // 32 x 513
    const int t   = blockIdx.x;
    const int tid = threadIdx.x;
#pragma unroll
    for (int it = 0; it < 16; it++) {
        int b  = it * 2 + (tid >> 7);
        int k4 = (tid & 127) << 2;
        float4 v = *(const float4*)&x[((size_t)b * SS + t) * II + k4];
        xs[b * 513 + k4 + 0] = v.x;
        xs[b * 513 + k4 + 1] = v.y;
        xs[b * 513 + k4 + 2] = v.z;
        xs[b * 513 + k4 + 3] = v.w;
    }
    __syncthreads();
#pragma unroll
    for (int it = 0; it < 16; it++) {
        int idx = tid + it * 256;        // 4096 = 128 kq x 32 b
        int kq  = idx >> 5;
        int b   = idx & 31;
        float4 v = make_float4(xs[b * 513 + 4 * kq + 0], xs[b * 513 + 4 * kq + 1],
                               xs[b * 513 + 4 * kq + 2], xs[b * 513 + 4 * kq + 3]);
        *(float4*)&g_xt[((size_t)t * 128 + kq) * 128 + b * 4] = v;
    }
}

// 16 rows x 32-k (16 u64); warp-uniform W (1 wf per LDS.128); 2 acc banks
__device__ __forceinline__ void fma_chunk32(
    const float* __restrict__ Wp, const u64* __restrict__ v2,
    float* __restrict__ sums, int kb)
{
#pragma unroll
    for (int r0 = 0; r0 < 16; r0 += 4) {
        u64 a0[4], a1[4];
#pragma unroll
        for (int rr = 0; rr < 4; rr++) { a0[rr] = 0ull; a1[rr] = 0ull; }
#pragma unroll
        for (int q = 0; q < 8; q++) {
#pragma unroll
            for (int rr = 0; rr < 4; rr++) {
                ulonglong2 wv = *(const ulonglong2*)&Wp[(r0 + rr) * 512 + kb + q * 4];
                a0[rr] = fma2(wv.x, v2[2 * q + 0], a0[rr]);
                a1[rr] = fma2(wv.y, v2[2 * q + 1], a1[rr]);
            }
        }
#pragma unroll
        for (int rr = 0; rr < 4; rr++) {
            float2 f = unpack2(add2(a0[rr], a1[rr]));
            sums[r0 + rr] += f.x + f.y;
        }
    }
}

// =====================================================================
// Kernel 2: persistent LSTM, local producer/consumer sync (no global
// barrier). 128 CTAs x 288 thr. Warp 0 = dedicated reducer/publisher;
// warps 1-8 = compute (k-chunk (w-1)*64). CTA owns 4 h-idx = 1 h-quad.
// Bucket b = CTAs 16b..16b+15 produce h-quads for k-chunk b*64.
// Worker step: x-FMA -> bucket wait -> h-FMA -> STS -> bar.arrive.
// Reducer step: bar.sync -> reduce + nonlin + h/out stores -> publish.
// =====================================================================
__global__ void __launch_bounds__(288, 1) lstm_rec(
    const float* __restrict__ Wih, const float* __restrict__ Whh,
    const float* __restrict__ bih, const float* __restrict__ bhh,
    const float* __restrict__ h0, const float* __restrict__ c0,
    float* __restrict__ out, int write_hc)
{
    extern __shared__ float sm[];
    float* Wih_s = sm;                 // 16 x 512 = 32KB
    float* Whh_s = sm + 8192;          // 32KB
    float* part  = sm + 16384;         // [16 rows][8 workers][32 b] = 16KB

    const int tid  = threadIdx.x;
    const int w    = tid >> 5;         // 0 = reducer, 1..8 = workers
    const int lane = tid & 31;         // lane = batch
    const int cta  = blockIdx.x;
    const int j0   = cta * 4;          // this CTA's h-quad

    // ---- load W slices (16 rows x 512 each), rows r = type*4 + jj ----
#pragma unroll
    for (int s = 0; s < 15; s++) {
        int idx = tid + s * 288;              // 4096 float4 slots
        if (idx < 4096) {
            int mat = idx >> 11;              // 0 = Wih, 1 = Whh
            int rr  = (idx & 2047) >> 7;
            int k4  = (idx & 127) << 2;
            int g   = (rr >> 2) * 512 + j0 + (rr & 3);
            float* dst = (mat ? Whh_s : Wih_s) + rr * 512 + k4;
            const float* src = (mat ? Whh : Wih) + (size_t)g * 512 + k4;
            *(float4*)dst = *(const float4*)src;
        }
    }
    __syncthreads();

    if (w == 0) {
        // ======================= reducer warp =======================
        float4 creg = *(const float4*)&c0[(size_t)lane * HH + j0];
        float4 bias[4];
#pragma unroll
        for (int t4 = 0; t4 < 4; t4++) {
            float4 b1 = *(const float4*)&bih[t4 * 512 + j0];
            float4 b2 = *(const float4*)&bhh[t4 * 512 + j0];
            bias[t4] = make_float4(b1.x + b2.x, b1.y + b2.y, b1.z + b2.z, b1.w + b2.w);
        }
        // publish h(0): store slice, then release-add all 4 bucket copies
        {
            float4 hv = *(const float4*)&h0[(size_t)lane * HH + j0];
            stcg_v4f32(&g_hb[0][(cta * 32 + lane) * 4], hv.x, hv.y, hv.z, hv.w);
            __syncwarp();
            if (lane < 4)
                asm volatile("red.release.gpu.global.add.u32 [%0], %1;"
                             :: "l"(&g_bkt[((cta >> 4) * 4 + lane) * 32]), "r"(1u)
                             : "memory");
        }

#pragma unroll 1
        for (int t = 0; t < SS; t++) {
            asm volatile("bar.sync 1, 288;" ::: "memory");   // workers' STS done

            float gate[4][4];   // [type][jj]
#pragma unroll
            for (int t4 = 0; t4 < 4; t4++) {
                float bv[4] = {bias[t4].x, bias[t4].y, bias[t4].z, bias[t4].w};
#pragma unroll
                for (int jj = 0; jj < 4; jj++) {
                    int r = t4 * 4 + jj;
                    float s = bv[jj];
#pragma unroll
                    for (int ww = 0; ww < 8; ww++)
                        s += part[r * 256 + ww * 32 + lane];
                    gate[t4][jj] = s;
                }
            }
            float hv[4], cv[4];
            float cr[4] = {creg.x, creg.y, creg.z, creg.w};
#pragma unroll
            for (int jj = 0; jj < 4; jj++) {
                float ig = sigmoid_fast(gate[0][jj]);
                float fg = sigmoid_fast(gate[1][jj]);
                float gg = tanh_fast(gate[2][jj]);
                float og = sigmoid_fast(gate[3][jj]);
                float c  = fg * cr[jj] + ig * gg;
                cv[jj] = c;
                hv[jj] = og * tanh_fast(c);
            }
            creg = make_float4(cv[0], cv[1], cv[2], cv[3]);

            stcg_v4f32(&g_hb[(t + 1) & 1][(cta * 32 + lane) * 4],
                       hv[0], hv[1], hv[2], hv[3]);
            *(float4*)&out[((size_t)lane * SS + t) * HH + j0] =
                make_float4(hv[0], hv[1], hv[2], hv[3]);
            if (t == SS - 1 && write_hc) {
                size_t base = (size_t)BB * SS * HH;
                *(float4*)&out[base + (size_t)lane * HH + j0] =
                    make_float4(hv[0], hv[1], hv[2], hv[3]);
                *(float4*)&out[base + (size_t)BB * HH + (size_t)lane * HH + j0] =
                    make_float4(cv[0], cv[1], cv[2], cv[3]);
            }
            __syncwarp();
            if (t < SS - 1 && lane < 4)
                asm volatile("red.release.gpu.global.add.u32 [%0], %1;"
                             :: "l"(&g_bkt[((cta >> 4) * 4 + lane) * 32]), "r"(1u)
                             : "memory");
        }
    } else {
        // ======================= worker warps =======================
        const int kw = w - 1;            // k-chunk index 0..7
        const int kb = kw * 64;
        const unsigned* ctr = &g_bkt[(kw * 4 + (cta & 3)) * 32];
        const ulonglong2* xq = (const ulonglong2*)g_xt;

#pragma unroll 1
        for (int t = 0; t < SS; t++) {
            float sums[16];
#pragma unroll
            for (int r = 0; r < 16; r++) sums[r] = 0.f;

            // ---- x phase (shadow work while producers publish h(t)) ----
            {
                u64 xv[32];
#pragma unroll
                for (int i = 0; i < 16; i++) {
                    ulonglong2 v = ldcg_v2u64(&xq[((size_t)t * 128 + kw * 16 + i) * 32 + lane]);
                    xv[2 * i + 0] = v.x;
                    xv[2 * i + 1] = v.y;
                }
                fma_chunk32(Wih_s, xv,      sums, kb);
                fma_chunk32(Wih_s, xv + 16, sums, kb + 32);
            }

            // ---- local wait: this k-chunk's 16 producers published h(t) ----
            while (ld_acq(ctr) < 16u * (unsigned)(t + 1)) { }

            // ---- h phase ----
            {
                const ulonglong2* hq = (const ulonglong2*)g_hb[t & 1];
                u64 hv[32];
#pragma unroll
                for (int i = 0; i < 16; i++) {
                    ulonglong2 v = ldcg_v2u64(&hq[(kw * 16 + i) * 32 + lane]);
                    hv[2 * i + 0] = v.x;
                    hv[2 * i + 1] = v.y;
                }
                fma_chunk32(Whh_s, hv,      sums, kb);
                fma_chunk32(Whh_s, hv + 16, sums, kb + 32);
            }

#pragma unroll
            for (int r = 0; r < 16; r++)
                part[r * 256 + kw * 32 + lane] = sums[r];
            // non-blocking: reducer's bar.sync consumes these arrivals.
            // Running ahead is safe: our t+1 STS is gated by the bucket
            // wait for t+1, which needs our OWN reducer's publish (after
            // it has read part for step t).
            asm volatile("bar.arrive 1, 288;" ::: "memory");
        }
    }

    // ---- cleanup: reset counters for graph replay ----
    __syncthreads();
    if (tid == 0) {
        unsigned old;
        asm volatile("atom.acq_rel.gpu.global.add.u32 %0, [%1], %2;"
                     : "=r"(old) : "l"(&g_end), "r"(1u));
        if (old == 127u) {
#pragma unroll
            for (int i = 0; i < 32; i++) g_bkt[i * 32] = 0u;
            g_end = 0u;
            __threadfence();
        }
    }
}

// =====================================================================
extern "C" void kernel_launch(void* const* d_in, const int* in_sizes, int n_in,
                              void* d_out, int out_size)
{
    const float* x   = (const float*)d_in[0];
    const float* Wih = (const float*)d_in[1];
    const float* Whh = (const float*)d_in[2];
    const float* bih = (const float*)d_in[3];
    const float* bhh = (const float*)d_in[4];
    const float* h0  = (const float*)d_in[5];
    const float* c0  = (const float*)d_in[6];
    float* out = (float*)d_out;

    long long need = (long long)BB * SS * HH + 2LL * BB * HH;
    int write_hc = ((long long)out_size >= need) ? 1 : 0;

    int xpose_smem = 32 * 513 * (int)sizeof(float);                  // ~64KB
    int rec_smem   = (32 * 512 + 16 * 256) * (int)sizeof(float);     // 80KB
    cudaFuncSetAttribute(xpose, cudaFuncAttributeMaxDynamicSharedMemorySize, xpose_smem);
    cudaFuncSetAttribute(lstm_rec, cudaFuncAttributeMaxDynamicSharedMemorySize, rec_smem);

    xpose<<<SS, 256, xpose_smem>>>(x);
    lstm_rec<<<128, 288, rec_smem>>>(Wih, Whh, bih, bhh, h0, c0, out, write_hc);
}